// round 5
// baseline (speedup 1.0000x reference)
#include <cuda_runtime.h>
#include <cuda_bf16.h>
#include <cuda_fp16.h>
#include <stdint.h>
#include <math.h>

// Problem constants
#define T_   32
#define B_   256
#define DIN_ 4196
#define H_   1024
#define C_   151

#define KP_IN    4224                // DIN padded to mult of 64
#define KTOT_IN  (2 * KP_IN)         // 8448 : fp16 2-term [Ah|Al] / [Bh|Bh]
#define KTOT_ST  (3 * H_)            // 3072 : bf16 3-term (proven accuracy)

// ---------------------------------------------------------------------------
// Scratch (static __device__ — no allocations allowed)
// ---------------------------------------------------------------------------
__device__ __half        g_A2h[(size_t)T_ * B_ * KTOT_IN];  // x split fp16 [8192, 8448]
__device__ __half        g_B2h[(size_t)6 * H_ * KTOT_IN];   // W_in split   [6144, 8448]
__device__ __nv_bfloat16 g_Bst[(size_t)5 * H_ * KTOT_ST];   // W_state bf16 [5120, 3072]
__device__ __nv_bfloat16 g_Ah [(size_t)B_ * KTOT_ST];       // h split bf16 [256, 3072]
__device__ float g_PI[(size_t)T_ * B_ * 6 * H_];
__device__ float g_PS[(size_t)B_ * 5 * H_];
__device__ float g_HS[(size_t)T_ * B_ * H_];
__device__ float g_CB[2 * (size_t)B_ * H_];

// ---------------------------------------------------------------------------
// PTX helpers (baseline compute_103-safe: cp.async / ldmatrix / mma.sync only)
// ---------------------------------------------------------------------------
__device__ __forceinline__ uint32_t smem_u32(const void* p) {
    uint32_t a;
    asm("{ .reg .u64 t; cvta.to.shared.u64 t, %1; cvt.u32.u64 %0, t; }"
        : "=r"(a) : "l"(p));
    return a;
}
__device__ __forceinline__ void cp16(uint32_t d, const void* s) {
    asm volatile("cp.async.cg.shared.global [%0], [%1], 16;" :: "r"(d), "l"(s));
}
__device__ __forceinline__ void cp_commit() {
    asm volatile("cp.async.commit_group;" ::: "memory");
}
template <int N> __device__ __forceinline__ void cp_wait() {
    asm volatile("cp.async.wait_group %0;" :: "n"(N) : "memory");
}
__device__ __forceinline__ void ldsm4(uint32_t* r, uint32_t addr) {
    asm volatile("ldmatrix.sync.aligned.m8n8.x4.shared.b16 {%0,%1,%2,%3}, [%4];"
                 : "=r"(r[0]), "=r"(r[1]), "=r"(r[2]), "=r"(r[3]) : "r"(addr));
}
__device__ __forceinline__ void mma_bf16(float* c, const uint32_t* a, const uint32_t* b) {
    asm volatile(
        "mma.sync.aligned.m16n8k16.row.col.f32.bf16.bf16.f32 "
        "{%0,%1,%2,%3}, {%4,%5,%6,%7}, {%8,%9}, {%0,%1,%2,%3};"
        : "+f"(c[0]), "+f"(c[1]), "+f"(c[2]), "+f"(c[3])
        : "r"(a[0]), "r"(a[1]), "r"(a[2]), "r"(a[3]), "r"(b[0]), "r"(b[1]));
}
__device__ __forceinline__ void mma_fp16(float* c, const uint32_t* a, const uint32_t* b) {
    asm volatile(
        "mma.sync.aligned.m16n8k16.row.col.f32.f16.f16.f32 "
        "{%0,%1,%2,%3}, {%4,%5,%6,%7}, {%8,%9}, {%0,%1,%2,%3};"
        : "+f"(c[0]), "+f"(c[1]), "+f"(c[2]), "+f"(c[3])
        : "r"(a[0]), "r"(a[1]), "r"(a[2]), "r"(a[3]), "r"(b[0]), "r"(b[1]));
}

// SW64 swizzle for 64B rows (8-row x 64B atoms): conflict-free ldmatrix
#define SW64(o) ((o) ^ (((o) >> 3) & 0x30))

// ---------------------------------------------------------------------------
// 16-bit tensor-core GEMM: C[M,N] = A[M,K]·B[N,K]^T + bias[N]
// A,B row-major 16-bit (K-contig). M%BM==0, N%BN==0, K%32==0.
// 8 warps (256 thr). Warp tile WM x WN. STAGES-deep cp.async pipeline.
// F16=1 -> fp16 operands, F16=0 -> bf16 operands.
// ---------------------------------------------------------------------------
template<int BM, int BN, int WM, int WN, int STAGES, int MAXCTA, int F16>
__global__ void __launch_bounds__(256, MAXCTA)
mma_gemm(const void* __restrict__ Av, const void* __restrict__ Bv,
         const float* __restrict__ bias, float* __restrict__ C,
         int M, int N, int K) {
    constexpr int STG = (BM + BN) * 64;      // bytes per stage (BK=32 elems = 64B/row)
    constexpr int MW = BM / WM;
    constexpr int NW = BN / WN;
    static_assert(MW * NW == 8, "need 8 warps");
    constexpr int MT = WM / 16;
    constexpr int NT = WN / 8;
    constexpr int NP = WN / 16;

    extern __shared__ char smem[];
    const uint32_t sb = smem_u32(smem);
    const char* A = (const char*)Av;
    const char* B = (const char*)Bv;
    const int tid = threadIdx.x;
    const int wid = tid >> 5;
    const int lane = tid & 31;
    const int wm = wid % MW;
    const int wn = wid / MW;
    const int l8 = lane & 7;
    const int sel = lane >> 3;
    const int m0 = blockIdx.y * BM;
    const int n0 = blockIdx.x * BN;
    const int KT = K / 32;

    auto load_stage = [&](int s, int kt) {
        const char* Ag = A + ((size_t)m0 * K + kt * 32) * 2;
        const char* Bg = B + ((size_t)n0 * K + kt * 32) * 2;
        const uint32_t stb = sb + s * STG;
#pragma unroll
        for (int i = tid; i < (BM + BN) * 4; i += 256) {
            if (i < BM * 4) {
                int row = i >> 2, c = i & 3;
                cp16(stb + SW64(row * 64 + c * 16), Ag + (size_t)row * K * 2 + c * 16);
            } else {
                int j = i - BM * 4;
                int row = j >> 2, c = j & 3;
                cp16(stb + BM * 64 + SW64(row * 64 + c * 16),
                     Bg + (size_t)row * K * 2 + c * 16);
            }
        }
    };

    float acc[MT][NT][4];
#pragma unroll
    for (int i = 0; i < MT; i++)
#pragma unroll
        for (int j = 0; j < NT; j++)
#pragma unroll
            for (int v = 0; v < 4; v++) acc[i][j][v] = 0.f;

#pragma unroll
    for (int s = 0; s < STAGES - 1; s++) {
        if (s < KT) load_stage(s, s);
        cp_commit();
    }

    for (int kt = 0; kt < KT; ++kt) {
        cp_wait<STAGES - 2>();
        __syncthreads();

        const int nk = kt + STAGES - 1;
        if (nk < KT) load_stage(nk % STAGES, nk);
        cp_commit();

        const uint32_t stb = sb + (kt % STAGES) * STG;
        const uint32_t stbB = stb + BM * 64;

#pragma unroll
        for (int ks = 0; ks < 2; ks++) {
            uint32_t ar[MT][4];
            uint32_t br[NP][4];
#pragma unroll
            for (int mt = 0; mt < MT; mt++) {
                int row = wm * WM + mt * 16 + l8 + (sel & 1) * 8;
                int ch = ks * 2 + (sel >> 1);
                ldsm4(ar[mt], stb + SW64(row * 64 + ch * 16));
            }
#pragma unroll
            for (int p = 0; p < NP; p++) {
                int row = wn * WN + p * 16 + l8 + (sel >> 1) * 8;
                int ch = ks * 2 + (sel & 1);
                ldsm4(br[p], stbB + SW64(row * 64 + ch * 16));
            }
#pragma unroll
            for (int mt = 0; mt < MT; mt++)
#pragma unroll
                for (int nt = 0; nt < NT; nt++) {
                    if (F16) mma_fp16(acc[mt][nt], ar[mt], &br[nt >> 1][(nt & 1) * 2]);
                    else     mma_bf16(acc[mt][nt], ar[mt], &br[nt >> 1][(nt & 1) * 2]);
                }
        }
    }

    // epilogue
    const int g4 = lane >> 2;
    const int t4 = lane & 3;
#pragma unroll
    for (int mt = 0; mt < MT; mt++) {
#pragma unroll
        for (int nt = 0; nt < NT; nt++) {
            const int r = m0 + wm * WM + mt * 16 + g4;
            const int col = n0 + wn * WN + nt * 8 + 2 * t4;
            const float b0 = bias[col], b1 = bias[col + 1];
            float2 v0 = make_float2(acc[mt][nt][0] + b0, acc[mt][nt][1] + b1);
            float2 v1 = make_float2(acc[mt][nt][2] + b0, acc[mt][nt][3] + b1);
            *reinterpret_cast<float2*>(&C[(size_t)r * N + col]) = v0;
            *reinterpret_cast<float2*>(&C[(size_t)(r + 8) * N + col]) = v1;
        }
    }
}

// ---------------------------------------------------------------------------
// Split conversions.
// fp16 2-term:  A row -> [hi|lo],  B row -> [hi|hi]
// bf16 3-term:  A row -> [hi|lo|hi],  B row -> [hi|hi|lo]
// ---------------------------------------------------------------------------
__global__ void splitA_f16(const float* __restrict__ src, __half* __restrict__ dst,
                           int K, int Kp, int total) {
    int idx = blockIdx.x * 256 + threadIdx.x;
    if (idx >= total) return;
    int r = idx / Kp, k = idx - r * Kp;
    float v = (k < K) ? src[(size_t)r * K + k] : 0.f;
    __half hi = __float2half(v);
    __half lo = __float2half(v - __half2float(hi));
    __half* row = dst + (size_t)r * 2 * Kp;
    row[k] = hi; row[Kp + k] = lo;
}
__global__ void splitB_f16(const float* __restrict__ src, __half* __restrict__ dst,
                           int K, int Kp, int total) {
    int idx = blockIdx.x * 256 + threadIdx.x;
    if (idx >= total) return;
    int r = idx / Kp, k = idx - r * Kp;
    float v = (k < K) ? src[(size_t)r * K + k] : 0.f;
    __half hi = __float2half(v);
    __half* row = dst + (size_t)r * 2 * Kp;
    row[k] = hi; row[Kp + k] = hi;
}
__global__ void splitA_bf(const float* __restrict__ src, __nv_bfloat16* __restrict__ dst,
                          int K, int Kp, int total) {
    int idx = blockIdx.x * 256 + threadIdx.x;
    if (idx >= total) return;
    int r = idx / Kp, k = idx - r * Kp;
    float v = (k < K) ? src[(size_t)r * K + k] : 0.f;
    __nv_bfloat16 hi = __float2bfloat16(v);
    __nv_bfloat16 lo = __float2bfloat16(v - __bfloat162float(hi));
    __nv_bfloat16* row = dst + (size_t)r * 3 * Kp;
    row[k] = hi; row[Kp + k] = lo; row[2 * Kp + k] = hi;
}
__global__ void splitB_bf(const float* __restrict__ src, __nv_bfloat16* __restrict__ dst,
                          int K, int Kp, int total) {
    int idx = blockIdx.x * 256 + threadIdx.x;
    if (idx >= total) return;
    int r = idx / Kp, k = idx - r * Kp;
    float v = (k < K) ? src[(size_t)r * K + k] : 0.f;
    __nv_bfloat16 hi = __float2bfloat16(v);
    __nv_bfloat16 lo = __float2bfloat16(v - __bfloat162float(hi));
    __nv_bfloat16* row = dst + (size_t)r * 3 * Kp;
    row[k] = hi; row[Kp + k] = hi; row[2 * Kp + k] = lo;
}

// ---------------------------------------------------------------------------
// Fused gates + recurrent-dropout + split-bf16 conversion of next h
// ---------------------------------------------------------------------------
__device__ __forceinline__ float sigf(float x) { return 1.f / (1.f + expf(-x)); }

__global__ void gates_kernel(const float* __restrict__ pi, const float* __restrict__ ps,
                             const float* __restrict__ c_in, float* __restrict__ c_out,
                             const float* __restrict__ mask, float* __restrict__ h_out,
                             __nv_bfloat16* __restrict__ Ah) {
    const int idx = blockIdx.x * blockDim.x + threadIdx.x;
    if (idx >= B_ * H_) return;
    const int b = idx / H_;
    const int j = idx - b * H_;
    const float* pib = pi + (size_t)b * 6 * H_;
    const float* psb = ps + (size_t)b * 5 * H_;

    const float i_g = sigf(pib[0 * H_ + j] + psb[0 * H_ + j]);
    const float f_g = sigf(pib[1 * H_ + j] + psb[1 * H_ + j]);
    const float m_i = tanhf(pib[2 * H_ + j] + psb[2 * H_ + j]);
    const float o_g = sigf(pib[3 * H_ + j] + psb[3 * H_ + j]);
    const float mem = i_g * m_i + f_g * c_in[idx];
    float out = o_g * tanhf(mem);
    const float hw = sigf(pib[4 * H_ + j] + psb[4 * H_ + j]);
    out = hw * out + (1.f - hw) * pib[5 * H_ + j];
    out *= mask[idx];
    c_out[idx] = mem;
    h_out[idx] = out;

    __nv_bfloat16 hi = __float2bfloat16(out);
    __nv_bfloat16 lo = __float2bfloat16(out - __bfloat162float(hi));
    __nv_bfloat16* row = Ah + (size_t)b * KTOT_ST;
    row[j] = hi; row[H_ + j] = lo; row[2 * H_ + j] = hi;
}

// ---------------------------------------------------------------------------
// fp32 SGEMM for the tiny output projection (N=151)
// ---------------------------------------------------------------------------
template<int BM, int BN, int TM, int TN>
__global__ void sgemm_bt(const float* __restrict__ A, const float* __restrict__ Bm,
                         const float* __restrict__ bias, float* __restrict__ C,
                         int M, int N, int K) {
    constexpr int BK = 16;
    constexpr int THREADS = (BM / TM) * (BN / TN);
    constexpr int PAD = 4;
    __shared__ float As[BK][BM + PAD];
    __shared__ float Bs[BK][BN + PAD];
    const int tid = threadIdx.x;
    const int m0 = blockIdx.y * BM;
    const int n0 = blockIdx.x * BN;
    const int tr = tid / (BN / TN);
    const int tc = tid % (BN / TN);
    float acc[TM][TN];
#pragma unroll
    for (int i = 0; i < TM; i++)
#pragma unroll
        for (int j = 0; j < TN; j++) acc[i][j] = 0.f;
    const int ktiles = (K + BK - 1) / BK;
    for (int kt = 0; kt < ktiles; ++kt) {
        const int k0 = kt * BK;
#pragma unroll
        for (int i = tid; i < BM * BK / 4; i += THREADS) {
            const int row = i / (BK / 4);
            const int kq = (i % (BK / 4)) * 4;
            float4 v = make_float4(0.f, 0.f, 0.f, 0.f);
            if (m0 + row < M && k0 + kq < K)
                v = *reinterpret_cast<const float4*>(&A[(size_t)(m0 + row) * K + k0 + kq]);
            As[kq + 0][row] = v.x; As[kq + 1][row] = v.y;
            As[kq + 2][row] = v.z; As[kq + 3][row] = v.w;
        }
#pragma unroll
        for (int i = tid; i < BN * BK / 4; i += THREADS) {
            const int row = i / (BK / 4);
            const int kq = (i % (BK / 4)) * 4;
            float4 v = make_float4(0.f, 0.f, 0.f, 0.f);
            if (n0 + row < N && k0 + kq < K)
                v = *reinterpret_cast<const float4*>(&Bm[(size_t)(n0 + row) * K + k0 + kq]);
            Bs[kq + 0][row] = v.x; Bs[kq + 1][row] = v.y;
            Bs[kq + 2][row] = v.z; Bs[kq + 3][row] = v.w;
        }
        __syncthreads();
#pragma unroll
        for (int kl = 0; kl < BK; ++kl) {
            float ra[TM], rb[TN];
#pragma unroll
            for (int i = 0; i < TM; i += 4) {
                float4 v = *reinterpret_cast<const float4*>(&As[kl][tr * TM + i]);
                ra[i] = v.x; ra[i + 1] = v.y; ra[i + 2] = v.z; ra[i + 3] = v.w;
            }
#pragma unroll
            for (int j = 0; j < TN; j += 4) {
                float4 v = *reinterpret_cast<const float4*>(&Bs[kl][tc * TN + j]);
                rb[j] = v.x; rb[j + 1] = v.y; rb[j + 2] = v.z; rb[j + 3] = v.w;
            }
#pragma unroll
            for (int i = 0; i < TM; i++)
#pragma unroll
                for (int j = 0; j < TN; j++)
                    acc[i][j] = fmaf(ra[i], rb[j], acc[i][j]);
        }
        __syncthreads();
    }
#pragma unroll
    for (int i = 0; i < TM; i++) {
        const int gm = m0 + tr * TM + i;
        if (gm >= M) continue;
#pragma unroll
        for (int j = 0; j < TN; j++) {
            const int gn = n0 + tc * TN + j;
            if (gn < N) C[(size_t)gm * N + gn] = acc[i][j] + bias[gn];
        }
    }
}

// ---------------------------------------------------------------------------
extern "C" void kernel_launch(void* const* d_in, const int* in_sizes, int n_in,
                              void* d_out, int out_size) {
    const float* x       = (const float*)d_in[0];
    const float* h0      = (const float*)d_in[1];
    const float* c0      = (const float*)d_in[2];
    const float* mask    = (const float*)d_in[3];
    const float* W_in    = (const float*)d_in[4];
    const float* b_in    = (const float*)d_in[5];
    const float* W_state = (const float*)d_in[6];
    const float* b_state = (const float*)d_in[7];
    const float* W_out   = (const float*)d_in[8];
    const float* b_out   = (const float*)d_in[9];
    float* out = (float*)d_out;

    __half *A2h, *B2h;
    __nv_bfloat16 *Bst, *Ah;
    float *PI, *PS, *HS, *CB;
    cudaGetSymbolAddress((void**)&A2h, g_A2h);
    cudaGetSymbolAddress((void**)&B2h, g_B2h);
    cudaGetSymbolAddress((void**)&Bst, g_Bst);
    cudaGetSymbolAddress((void**)&Ah, g_Ah);
    cudaGetSymbolAddress((void**)&PI, g_PI);
    cudaGetSymbolAddress((void**)&PS, g_PS);
    cudaGetSymbolAddress((void**)&HS, g_HS);
    cudaGetSymbolAddress((void**)&CB, g_CB);

    // Big GEMM: 128x128 CTA, 32x64 warp, 4 stages, 2 CTA/SM  (round-3 winner)
    constexpr int SMEM_BIG = (128 + 128) * 64 * 4;   // 65536
    // Recurrence: 64x128 CTA, 32x32 warp, 4 stages, 2 CTA/SM
    constexpr int SMEM_REC = (64 + 128) * 64 * 4;    // 49152
    cudaFuncSetAttribute((const void*)mma_gemm<128, 128, 32, 64, 4, 2, 1>,
                         cudaFuncAttributeMaxDynamicSharedMemorySize, SMEM_BIG);
    cudaFuncSetAttribute((const void*)mma_gemm<64, 128, 32, 32, 4, 2, 0>,
                         cudaFuncAttributeMaxDynamicSharedMemorySize, SMEM_REC);

    const size_t BH = (size_t)B_ * H_;

    // 0,1: fp16 2-term conversions for the input projection
    {
        int tot = T_ * B_ * KP_IN;
        splitA_f16<<<(tot + 255) / 256, 256>>>(x, A2h, DIN_, KP_IN, tot);
    }
    {
        int tot = 6 * H_ * KP_IN;
        splitB_f16<<<(tot + 255) / 256, 256>>>(W_in, B2h, DIN_, KP_IN, tot);
    }
    // 2: bf16 3-term for W_state
    {
        int tot = 5 * H_ * H_;
        splitB_bf<<<(tot + 255) / 256, 256>>>(W_state, Bst, H_, H_, tot);
    }

    // 3: Input projection PI[8192, 6144] = x·W_in^T + b_in  (fp16 tensor cores)
    {
        dim3 grid((6 * H_) / 128, (T_ * B_) / 128);
        mma_gemm<128, 128, 32, 64, 4, 2, 1><<<grid, 256, SMEM_BIG>>>(
            A2h, B2h, b_in, PI, T_ * B_, 6 * H_, KTOT_IN);
    }

    // 4: h0 split (needed only by recurrence)
    {
        int tot = B_ * H_;
        splitA_bf<<<(tot + 255) / 256, 256>>>(h0, Ah, H_, H_, tot);
    }

    // Sequential recurrence (bf16 3-term, proven accuracy)
    for (int t = 0; t < T_; ++t) {
        const float* csrc = (t == 0) ? c0 : CB + (size_t)((t - 1) & 1) * BH;
        float* cdst = CB + (size_t)(t & 1) * BH;
        float* hdst = HS + (size_t)t * BH;
        const float* pit = PI + (size_t)t * B_ * 6 * H_;

        dim3 grid((5 * H_) / 128, B_ / 64);
        mma_gemm<64, 128, 32, 32, 4, 2, 0><<<grid, 256, SMEM_REC>>>(
            Ah, Bst, b_state, PS, B_, 5 * H_, KTOT_ST);
        gates_kernel<<<(B_ * H_) / 256, 256>>>(pit, PS, csrc, cdst, mask, hdst, Ah);
    }

    // Output projection (fp32, tiny N)
    {
        dim3 grid((C_ + 63) / 64, (T_ * B_) / 64);
        sgemm_bt<64, 64, 4, 4><<<grid, 256>>>(HS, W_out, b_out, out,
                                              T_ * B_, C_, H_);
    }
}

// round 6
// speedup vs baseline: 1.5501x; 1.5501x over previous
#include <cuda_runtime.h>
#include <cuda_bf16.h>
#include <cuda_fp16.h>
#include <stdint.h>
#include <math.h>

// Problem constants
#define T_   32
#define B_   256
#define DIN_ 4196
#define H_   1024
#define C_   151

#define KP_IN    4224                // DIN padded to mult of 64
#define KTOT_IN  (2 * KP_IN)         // 8448 : fp16 2-term [Ah|Al] / [Bh|Bh]
#define KTOT_ST  (3 * H_)            // 3072 : bf16 3-term (proven accuracy)

#define NCHUNK   8                   // input-projection chunks (4 timesteps each)
#define CH_ROWS  (T_ * B_ / NCHUNK)  // 1024 rows per chunk

// ---------------------------------------------------------------------------
// Scratch (static __device__ — no allocations allowed)
// ---------------------------------------------------------------------------
__device__ __half        g_A2h[(size_t)T_ * B_ * KTOT_IN];  // x split fp16 [8192, 8448]
__device__ __half        g_B2h[(size_t)6 * H_ * KTOT_IN];   // W_in split   [6144, 8448]
__device__ __nv_bfloat16 g_Bst[(size_t)5 * H_ * KTOT_ST];   // W_state bf16 [5120, 3072]
__device__ __nv_bfloat16 g_Ah [(size_t)B_ * KTOT_ST];       // h split bf16 [256, 3072]
__device__ float g_PI[(size_t)T_ * B_ * 6 * H_];
__device__ float g_PS[(size_t)B_ * 5 * H_];
__device__ float g_HS[(size_t)T_ * B_ * H_];
__device__ float g_CB[2 * (size_t)B_ * H_];

// ---------------------------------------------------------------------------
// PTX helpers (baseline compute_103-safe: cp.async / ldmatrix / mma.sync only)
// ---------------------------------------------------------------------------
__device__ __forceinline__ uint32_t smem_u32(const void* p) {
    uint32_t a;
    asm("{ .reg .u64 t; cvta.to.shared.u64 t, %1; cvt.u32.u64 %0, t; }"
        : "=r"(a) : "l"(p));
    return a;
}
__device__ __forceinline__ void cp16(uint32_t d, const void* s) {
    asm volatile("cp.async.cg.shared.global [%0], [%1], 16;" :: "r"(d), "l"(s));
}
__device__ __forceinline__ void cp_commit() {
    asm volatile("cp.async.commit_group;" ::: "memory");
}
template <int N> __device__ __forceinline__ void cp_wait() {
    asm volatile("cp.async.wait_group %0;" :: "n"(N) : "memory");
}
__device__ __forceinline__ void ldsm4(uint32_t* r, uint32_t addr) {
    asm volatile("ldmatrix.sync.aligned.m8n8.x4.shared.b16 {%0,%1,%2,%3}, [%4];"
                 : "=r"(r[0]), "=r"(r[1]), "=r"(r[2]), "=r"(r[3]) : "r"(addr));
}
__device__ __forceinline__ void mma_bf16(float* c, const uint32_t* a, const uint32_t* b) {
    asm volatile(
        "mma.sync.aligned.m16n8k16.row.col.f32.bf16.bf16.f32 "
        "{%0,%1,%2,%3}, {%4,%5,%6,%7}, {%8,%9}, {%0,%1,%2,%3};"
        : "+f"(c[0]), "+f"(c[1]), "+f"(c[2]), "+f"(c[3])
        : "r"(a[0]), "r"(a[1]), "r"(a[2]), "r"(a[3]), "r"(b[0]), "r"(b[1]));
}
__device__ __forceinline__ void mma_fp16(float* c, const uint32_t* a, const uint32_t* b) {
    asm volatile(
        "mma.sync.aligned.m16n8k16.row.col.f32.f16.f16.f32 "
        "{%0,%1,%2,%3}, {%4,%5,%6,%7}, {%8,%9}, {%0,%1,%2,%3};"
        : "+f"(c[0]), "+f"(c[1]), "+f"(c[2]), "+f"(c[3])
        : "r"(a[0]), "r"(a[1]), "r"(a[2]), "r"(a[3]), "r"(b[0]), "r"(b[1]));
}

// SW64 swizzle for 64B rows (8-row x 64B atoms): conflict-free ldmatrix
#define SW64(o) ((o) ^ (((o) >> 3) & 0x30))

// ---------------------------------------------------------------------------
// 16-bit tensor-core GEMM: C[M,N] = A[M,K]·B[N,K]^T + bias[N]
// ---------------------------------------------------------------------------
template<int BM, int BN, int WM, int WN, int STAGES, int MAXCTA, int F16>
__global__ void __launch_bounds__(256, MAXCTA)
mma_gemm(const void* __restrict__ Av, const void* __restrict__ Bv,
         const float* __restrict__ bias, float* __restrict__ C,
         int M, int N, int K) {
    constexpr int STG = (BM + BN) * 64;
    constexpr int MW = BM / WM;
    constexpr int NW = BN / WN;
    static_assert(MW * NW == 8, "need 8 warps");
    constexpr int MT = WM / 16;
    constexpr int NT = WN / 8;
    constexpr int NP = WN / 16;

    extern __shared__ char smem[];
    const uint32_t sb = smem_u32(smem);
    const char* A = (const char*)Av;
    const char* B = (const char*)Bv;
    const int tid = threadIdx.x;
    const int wid = tid >> 5;
    const int lane = tid & 31;
    const int wm = wid % MW;
    const int wn = wid / MW;
    const int l8 = lane & 7;
    const int sel = lane >> 3;
    const int m0 = blockIdx.y * BM;
    const int n0 = blockIdx.x * BN;
    const int KT = K / 32;

    auto load_stage = [&](int s, int kt) {
        const char* Ag = A + ((size_t)m0 * K + kt * 32) * 2;
        const char* Bg = B + ((size_t)n0 * K + kt * 32) * 2;
        const uint32_t stb = sb + s * STG;
#pragma unroll
        for (int i = tid; i < (BM + BN) * 4; i += 256) {
            if (i < BM * 4) {
                int row = i >> 2, c = i & 3;
                cp16(stb + SW64(row * 64 + c * 16), Ag + (size_t)row * K * 2 + c * 16);
            } else {
                int j = i - BM * 4;
                int row = j >> 2, c = j & 3;
                cp16(stb + BM * 64 + SW64(row * 64 + c * 16),
                     Bg + (size_t)row * K * 2 + c * 16);
            }
        }
    };

    float acc[MT][NT][4];
#pragma unroll
    for (int i = 0; i < MT; i++)
#pragma unroll
        for (int j = 0; j < NT; j++)
#pragma unroll
            for (int v = 0; v < 4; v++) acc[i][j][v] = 0.f;

#pragma unroll
    for (int s = 0; s < STAGES - 1; s++) {
        if (s < KT) load_stage(s, s);
        cp_commit();
    }

    for (int kt = 0; kt < KT; ++kt) {
        cp_wait<STAGES - 2>();
        __syncthreads();

        const int nk = kt + STAGES - 1;
        if (nk < KT) load_stage(nk % STAGES, nk);
        cp_commit();

        const uint32_t stb = sb + (kt % STAGES) * STG;
        const uint32_t stbB = stb + BM * 64;

#pragma unroll
        for (int ks = 0; ks < 2; ks++) {
            uint32_t ar[MT][4];
            uint32_t br[NP][4];
#pragma unroll
            for (int mt = 0; mt < MT; mt++) {
                int row = wm * WM + mt * 16 + l8 + (sel & 1) * 8;
                int ch = ks * 2 + (sel >> 1);
                ldsm4(ar[mt], stb + SW64(row * 64 + ch * 16));
            }
#pragma unroll
            for (int p = 0; p < NP; p++) {
                int row = wn * WN + p * 16 + l8 + (sel >> 1) * 8;
                int ch = ks * 2 + (sel & 1);
                ldsm4(br[p], stbB + SW64(row * 64 + ch * 16));
            }
#pragma unroll
            for (int mt = 0; mt < MT; mt++)
#pragma unroll
                for (int nt = 0; nt < NT; nt++) {
                    if (F16) mma_fp16(acc[mt][nt], ar[mt], &br[nt >> 1][(nt & 1) * 2]);
                    else     mma_bf16(acc[mt][nt], ar[mt], &br[nt >> 1][(nt & 1) * 2]);
                }
        }
    }

    const int g4 = lane >> 2;
    const int t4 = lane & 3;
#pragma unroll
    for (int mt = 0; mt < MT; mt++) {
#pragma unroll
        for (int nt = 0; nt < NT; nt++) {
            const int r = m0 + wm * WM + mt * 16 + g4;
            const int col = n0 + wn * WN + nt * 8 + 2 * t4;
            const float b0 = bias[col], b1 = bias[col + 1];
            float2 v0 = make_float2(acc[mt][nt][0] + b0, acc[mt][nt][1] + b1);
            float2 v1 = make_float2(acc[mt][nt][2] + b0, acc[mt][nt][3] + b1);
            *reinterpret_cast<float2*>(&C[(size_t)r * N + col]) = v0;
            *reinterpret_cast<float2*>(&C[(size_t)(r + 8) * N + col]) = v1;
        }
    }
}

// ---------------------------------------------------------------------------
// Split conversions
// ---------------------------------------------------------------------------
__global__ void splitA_f16(const float* __restrict__ src, __half* __restrict__ dst,
                           int K, int Kp, int total) {
    int idx = blockIdx.x * 256 + threadIdx.x;
    if (idx >= total) return;
    int r = idx / Kp, k = idx - r * Kp;
    float v = (k < K) ? src[(size_t)r * K + k] : 0.f;
    __half hi = __float2half(v);
    __half lo = __float2half(v - __half2float(hi));
    __half* row = dst + (size_t)r * 2 * Kp;
    row[k] = hi; row[Kp + k] = lo;
}
__global__ void splitB_f16(const float* __restrict__ src, __half* __restrict__ dst,
                           int K, int Kp, int total) {
    int idx = blockIdx.x * 256 + threadIdx.x;
    if (idx >= total) return;
    int r = idx / Kp, k = idx - r * Kp;
    float v = (k < K) ? src[(size_t)r * K + k] : 0.f;
    __half hi = __float2half(v);
    __half* row = dst + (size_t)r * 2 * Kp;
    row[k] = hi; row[Kp + k] = hi;
}
__global__ void splitA_bf(const float* __restrict__ src, __nv_bfloat16* __restrict__ dst,
                          int K, int Kp, int total) {
    int idx = blockIdx.x * 256 + threadIdx.x;
    if (idx >= total) return;
    int r = idx / Kp, k = idx - r * Kp;
    float v = (k < K) ? src[(size_t)r * K + k] : 0.f;
    __nv_bfloat16 hi = __float2bfloat16(v);
    __nv_bfloat16 lo = __float2bfloat16(v - __bfloat162float(hi));
    __nv_bfloat16* row = dst + (size_t)r * 3 * Kp;
    row[k] = hi; row[Kp + k] = lo; row[2 * Kp + k] = hi;
}
__global__ void splitB_bf(const float* __restrict__ src, __nv_bfloat16* __restrict__ dst,
                          int K, int Kp, int total) {
    int idx = blockIdx.x * 256 + threadIdx.x;
    if (idx >= total) return;
    int r = idx / Kp, k = idx - r * Kp;
    float v = (k < K) ? src[(size_t)r * K + k] : 0.f;
    __nv_bfloat16 hi = __float2bfloat16(v);
    __nv_bfloat16 lo = __float2bfloat16(v - __bfloat162float(hi));
    __nv_bfloat16* row = dst + (size_t)r * 3 * Kp;
    row[k] = hi; row[Kp + k] = hi; row[2 * Kp + k] = lo;
}

// ---------------------------------------------------------------------------
// Fused gates + recurrent-dropout + split-bf16 conversion of next h
// ---------------------------------------------------------------------------
__device__ __forceinline__ float sigf(float x) { return 1.f / (1.f + expf(-x)); }

__global__ void gates_kernel(const float* __restrict__ pi, const float* __restrict__ ps,
                             const float* __restrict__ c_in, float* __restrict__ c_out,
                             const float* __restrict__ mask, float* __restrict__ h_out,
                             __nv_bfloat16* __restrict__ Ah) {
    const int idx = blockIdx.x * blockDim.x + threadIdx.x;
    if (idx >= B_ * H_) return;
    const int b = idx / H_;
    const int j = idx - b * H_;
    const float* pib = pi + (size_t)b * 6 * H_;
    const float* psb = ps + (size_t)b * 5 * H_;

    const float i_g = sigf(pib[0 * H_ + j] + psb[0 * H_ + j]);
    const float f_g = sigf(pib[1 * H_ + j] + psb[1 * H_ + j]);
    const float m_i = tanhf(pib[2 * H_ + j] + psb[2 * H_ + j]);
    const float o_g = sigf(pib[3 * H_ + j] + psb[3 * H_ + j]);
    const float mem = i_g * m_i + f_g * c_in[idx];
    float out = o_g * tanhf(mem);
    const float hw = sigf(pib[4 * H_ + j] + psb[4 * H_ + j]);
    out = hw * out + (1.f - hw) * pib[5 * H_ + j];
    out *= mask[idx];
    c_out[idx] = mem;
    h_out[idx] = out;

    __nv_bfloat16 hi = __float2bfloat16(out);
    __nv_bfloat16 lo = __float2bfloat16(out - __bfloat162float(hi));
    __nv_bfloat16* row = Ah + (size_t)b * KTOT_ST;
    row[j] = hi; row[H_ + j] = lo; row[2 * H_ + j] = hi;
}

// ---------------------------------------------------------------------------
// fp32 SGEMM for the tiny output projection (N=151)
// ---------------------------------------------------------------------------
template<int BM, int BN, int TM, int TN>
__global__ void sgemm_bt(const float* __restrict__ A, const float* __restrict__ Bm,
                         const float* __restrict__ bias, float* __restrict__ C,
                         int M, int N, int K) {
    constexpr int BK = 16;
    constexpr int THREADS = (BM / TM) * (BN / TN);
    constexpr int PAD = 4;
    __shared__ float As[BK][BM + PAD];
    __shared__ float Bs[BK][BN + PAD];
    const int tid = threadIdx.x;
    const int m0 = blockIdx.y * BM;
    const int n0 = blockIdx.x * BN;
    const int tr = tid / (BN / TN);
    const int tc = tid % (BN / TN);
    float acc[TM][TN];
#pragma unroll
    for (int i = 0; i < TM; i++)
#pragma unroll
        for (int j = 0; j < TN; j++) acc[i][j] = 0.f;
    const int ktiles = (K + BK - 1) / BK;
    for (int kt = 0; kt < ktiles; ++kt) {
        const int k0 = kt * BK;
#pragma unroll
        for (int i = tid; i < BM * BK / 4; i += THREADS) {
            const int row = i / (BK / 4);
            const int kq = (i % (BK / 4)) * 4;
            float4 v = make_float4(0.f, 0.f, 0.f, 0.f);
            if (m0 + row < M && k0 + kq < K)
                v = *reinterpret_cast<const float4*>(&A[(size_t)(m0 + row) * K + k0 + kq]);
            As[kq + 0][row] = v.x; As[kq + 1][row] = v.y;
            As[kq + 2][row] = v.z; As[kq + 3][row] = v.w;
        }
#pragma unroll
        for (int i = tid; i < BN * BK / 4; i += THREADS) {
            const int row = i / (BK / 4);
            const int kq = (i % (BK / 4)) * 4;
            float4 v = make_float4(0.f, 0.f, 0.f, 0.f);
            if (n0 + row < N && k0 + kq < K)
                v = *reinterpret_cast<const float4*>(&Bm[(size_t)(n0 + row) * K + k0 + kq]);
            Bs[kq + 0][row] = v.x; Bs[kq + 1][row] = v.y;
            Bs[kq + 2][row] = v.z; Bs[kq + 3][row] = v.w;
        }
        __syncthreads();
#pragma unroll
        for (int kl = 0; kl < BK; ++kl) {
            float ra[TM], rb[TN];
#pragma unroll
            for (int i = 0; i < TM; i += 4) {
                float4 v = *reinterpret_cast<const float4*>(&As[kl][tr * TM + i]);
                ra[i] = v.x; ra[i + 1] = v.y; ra[i + 2] = v.z; ra[i + 3] = v.w;
            }
#pragma unroll
            for (int j = 0; j < TN; j += 4) {
                float4 v = *reinterpret_cast<const float4*>(&Bs[kl][tc * TN + j]);
                rb[j] = v.x; rb[j + 1] = v.y; rb[j + 2] = v.z; rb[j + 3] = v.w;
            }
#pragma unroll
            for (int i = 0; i < TM; i++)
#pragma unroll
                for (int j = 0; j < TN; j++)
                    acc[i][j] = fmaf(ra[i], rb[j], acc[i][j]);
        }
        __syncthreads();
    }
#pragma unroll
    for (int i = 0; i < TM; i++) {
        const int gm = m0 + tr * TM + i;
        if (gm >= M) continue;
#pragma unroll
        for (int j = 0; j < TN; j++) {
            const int gn = n0 + tc * TN + j;
            if (gn < N) C[(size_t)gm * N + gn] = acc[i][j] + bias[gn];
        }
    }
}

// ---------------------------------------------------------------------------
extern "C" void kernel_launch(void* const* d_in, const int* in_sizes, int n_in,
                              void* d_out, int out_size) {
    const float* x       = (const float*)d_in[0];
    const float* h0      = (const float*)d_in[1];
    const float* c0      = (const float*)d_in[2];
    const float* mask    = (const float*)d_in[3];
    const float* W_in    = (const float*)d_in[4];
    const float* b_in    = (const float*)d_in[5];
    const float* W_state = (const float*)d_in[6];
    const float* b_state = (const float*)d_in[7];
    const float* W_out   = (const float*)d_in[8];
    const float* b_out   = (const float*)d_in[9];
    float* out = (float*)d_out;

    __half *A2h, *B2h;
    __nv_bfloat16 *Bst, *Ah;
    float *PI, *PS, *HS, *CB;
    cudaGetSymbolAddress((void**)&A2h, g_A2h);
    cudaGetSymbolAddress((void**)&B2h, g_B2h);
    cudaGetSymbolAddress((void**)&Bst, g_Bst);
    cudaGetSymbolAddress((void**)&Ah, g_Ah);
    cudaGetSymbolAddress((void**)&PI, g_PI);
    cudaGetSymbolAddress((void**)&PS, g_PS);
    cudaGetSymbolAddress((void**)&HS, g_HS);
    cudaGetSymbolAddress((void**)&CB, g_CB);

    // One-time side-stream + events (no device memory involved)
    static cudaStream_t s2 = nullptr;
    static cudaEvent_t evFork = nullptr;
    static cudaEvent_t evPI[NCHUNK];
    if (!s2) {
        cudaStreamCreateWithFlags(&s2, cudaStreamNonBlocking);
        cudaEventCreateWithFlags(&evFork, cudaEventDisableTiming);
        for (int i = 0; i < NCHUNK; i++)
            cudaEventCreateWithFlags(&evPI[i], cudaEventDisableTiming);
    }

    constexpr int SMEM_BIG = (128 + 128) * 64 * 4;   // 65536
    constexpr int SMEM_REC = (64 + 128) * 64 * 4;    // 49152
    cudaFuncSetAttribute((const void*)mma_gemm<128, 128, 32, 64, 4, 2, 1>,
                         cudaFuncAttributeMaxDynamicSharedMemorySize, SMEM_BIG);
    cudaFuncSetAttribute((const void*)mma_gemm<64, 128, 32, 32, 4, 2, 0>,
                         cudaFuncAttributeMaxDynamicSharedMemorySize, SMEM_REC);

    const size_t BH = (size_t)B_ * H_;

    // ---- fork side stream off the capture stream ----
    cudaEventRecord(evFork, 0);
    cudaStreamWaitEvent(s2, evFork, 0);

    // ---- stream s2: input-projection pipeline (independent of recurrence) ----
    {
        int tot = T_ * B_ * KP_IN;
        splitA_f16<<<(tot + 255) / 256, 256, 0, s2>>>(x, A2h, DIN_, KP_IN, tot);
    }
    {
        int tot = 6 * H_ * KP_IN;
        splitB_f16<<<(tot + 255) / 256, 256, 0, s2>>>(W_in, B2h, DIN_, KP_IN, tot);
    }
    for (int c = 0; c < NCHUNK; c++) {
        dim3 grid((6 * H_) / 128, CH_ROWS / 128);
        mma_gemm<128, 128, 32, 64, 4, 2, 1><<<grid, 256, SMEM_BIG, s2>>>(
            A2h + (size_t)c * CH_ROWS * KTOT_IN, B2h, b_in,
            PI + (size_t)c * CH_ROWS * 6 * H_, CH_ROWS, 6 * H_, KTOT_IN);
        cudaEventRecord(evPI[c], s2);
    }

    // ---- capture stream: recurrence chain ----
    {
        int tot = 5 * H_ * H_;
        splitB_bf<<<(tot + 255) / 256, 256>>>(W_state, Bst, H_, H_, tot);
    }
    {
        int tot = B_ * H_;
        splitA_bf<<<(tot + 255) / 256, 256>>>(h0, Ah, H_, H_, tot);
    }

    for (int t = 0; t < T_; ++t) {
        const float* csrc = (t == 0) ? c0 : CB + (size_t)((t - 1) & 1) * BH;
        float* cdst = CB + (size_t)(t & 1) * BH;
        float* hdst = HS + (size_t)t * BH;
        const float* pit = PI + (size_t)t * B_ * 6 * H_;

        dim3 grid((5 * H_) / 128, B_ / 64);
        mma_gemm<64, 128, 32, 32, 4, 2, 0><<<grid, 256, SMEM_REC>>>(
            Ah, Bst, b_state, PS, B_, 5 * H_, KTOT_ST);

        if ((t & 3) == 0)                       // gates(t) needs PI chunk t/4
            cudaStreamWaitEvent(0, evPI[t >> 2], 0);
        gates_kernel<<<(B_ * H_) / 256, 256>>>(pit, PS, csrc, cdst, mask, hdst, Ah);
    }

    // Output projection (fp32, tiny N) — depends only on HS (capture stream)
    {
        dim3 grid((C_ + 63) / 64, (T_ * B_) / 64);
        sgemm_bt<64, 64, 4, 4><<<grid, 256>>>(HS, W_out, b_out, out,
                                              T_ * B_, C_, H_);
    }
}

// round 7
// speedup vs baseline: 2.0601x; 1.3290x over previous
#include <cuda_runtime.h>
#include <cuda_bf16.h>
#include <cuda_fp16.h>
#include <stdint.h>
#include <math.h>

// Problem constants
#define T_   32
#define B_   256
#define DIN_ 4196
#define H_   1024
#define C_   151

#define KP_IN    4224                // DIN padded to mult of 64 (single-term fp16)
#define KTOT_ST  (3 * H_)            // 3072 : bf16 3-term recurrence (proven)

#define NCHUNK   8                   // input-projection chunks (4 timesteps each)
#define CH_ROWS  (T_ * B_ / NCHUNK)  // 1024 rows per chunk

// ---------------------------------------------------------------------------
// Scratch (static __device__ — no allocations allowed)
// ---------------------------------------------------------------------------
__device__ __half        g_A2h[(size_t)T_ * B_ * KP_IN];    // x fp16  [8192, 4224]
__device__ __half        g_B2h[(size_t)6 * H_ * KP_IN];     // W_in    [6144, 4224]
__device__ __nv_bfloat16 g_Bst[(size_t)5 * H_ * KTOT_ST];   // W_state [5120, 3072]
__device__ __nv_bfloat16 g_Ah [(size_t)B_ * KTOT_ST];       // h split [256, 3072]
__device__ float g_PI[(size_t)T_ * B_ * 6 * H_];
__device__ float g_PS[(size_t)B_ * 5 * H_];
__device__ float g_HS[(size_t)T_ * B_ * H_];
__device__ float g_CB[2 * (size_t)B_ * H_];

// ---------------------------------------------------------------------------
// PTX helpers (baseline compute_103-safe: cp.async / ldmatrix / mma.sync only)
// ---------------------------------------------------------------------------
__device__ __forceinline__ uint32_t smem_u32(const void* p) {
    uint32_t a;
    asm("{ .reg .u64 t; cvta.to.shared.u64 t, %1; cvt.u32.u64 %0, t; }"
        : "=r"(a) : "l"(p));
    return a;
}
__device__ __forceinline__ void cp16(uint32_t d, const void* s) {
    asm volatile("cp.async.cg.shared.global [%0], [%1], 16;" :: "r"(d), "l"(s));
}
__device__ __forceinline__ void cp_commit() {
    asm volatile("cp.async.commit_group;" ::: "memory");
}
template <int N> __device__ __forceinline__ void cp_wait() {
    asm volatile("cp.async.wait_group %0;" :: "n"(N) : "memory");
}
__device__ __forceinline__ void ldsm4(uint32_t* r, uint32_t addr) {
    asm volatile("ldmatrix.sync.aligned.m8n8.x4.shared.b16 {%0,%1,%2,%3}, [%4];"
                 : "=r"(r[0]), "=r"(r[1]), "=r"(r[2]), "=r"(r[3]) : "r"(addr));
}
__device__ __forceinline__ void mma_bf16(float* c, const uint32_t* a, const uint32_t* b) {
    asm volatile(
        "mma.sync.aligned.m16n8k16.row.col.f32.bf16.bf16.f32 "
        "{%0,%1,%2,%3}, {%4,%5,%6,%7}, {%8,%9}, {%0,%1,%2,%3};"
        : "+f"(c[0]), "+f"(c[1]), "+f"(c[2]), "+f"(c[3])
        : "r"(a[0]), "r"(a[1]), "r"(a[2]), "r"(a[3]), "r"(b[0]), "r"(b[1]));
}
__device__ __forceinline__ void mma_fp16(float* c, const uint32_t* a, const uint32_t* b) {
    asm volatile(
        "mma.sync.aligned.m16n8k16.row.col.f32.f16.f16.f32 "
        "{%0,%1,%2,%3}, {%4,%5,%6,%7}, {%8,%9}, {%0,%1,%2,%3};"
        : "+f"(c[0]), "+f"(c[1]), "+f"(c[2]), "+f"(c[3])
        : "r"(a[0]), "r"(a[1]), "r"(a[2]), "r"(a[3]), "r"(b[0]), "r"(b[1]));
}

// SW64 swizzle for 64B rows (8-row x 64B atoms): conflict-free ldmatrix
#define SW64(o) ((o) ^ (((o) >> 3) & 0x30))

// ---------------------------------------------------------------------------
// 16-bit tensor-core GEMM: C[M,N] = A[M,K]·B[N,K]^T + bias[N]
// ---------------------------------------------------------------------------
template<int BM, int BN, int WM, int WN, int STAGES, int MAXCTA, int F16>
__global__ void __launch_bounds__(256, MAXCTA)
mma_gemm(const void* __restrict__ Av, const void* __restrict__ Bv,
         const float* __restrict__ bias, float* __restrict__ C,
         int M, int N, int K) {
    constexpr int STG = (BM + BN) * 64;
    constexpr int MW = BM / WM;
    constexpr int NW = BN / WN;
    static_assert(MW * NW == 8, "need 8 warps");
    constexpr int MT = WM / 16;
    constexpr int NT = WN / 8;
    constexpr int NP = WN / 16;

    extern __shared__ char smem[];
    const uint32_t sb = smem_u32(smem);
    const char* A = (const char*)Av;
    const char* B = (const char*)Bv;
    const int tid = threadIdx.x;
    const int wid = tid >> 5;
    const int lane = tid & 31;
    const int wm = wid % MW;
    const int wn = wid / MW;
    const int l8 = lane & 7;
    const int sel = lane >> 3;
    const int m0 = blockIdx.y * BM;
    const int n0 = blockIdx.x * BN;
    const int KT = K / 32;

    auto load_stage = [&](int s, int kt) {
        const char* Ag = A + ((size_t)m0 * K + kt * 32) * 2;
        const char* Bg = B + ((size_t)n0 * K + kt * 32) * 2;
        const uint32_t stb = sb + s * STG;
#pragma unroll
        for (int i = tid; i < (BM + BN) * 4; i += 256) {
            if (i < BM * 4) {
                int row = i >> 2, c = i & 3;
                cp16(stb + SW64(row * 64 + c * 16), Ag + (size_t)row * K * 2 + c * 16);
            } else {
                int j = i - BM * 4;
                int row = j >> 2, c = j & 3;
                cp16(stb + BM * 64 + SW64(row * 64 + c * 16),
                     Bg + (size_t)row * K * 2 + c * 16);
            }
        }
    };

    float acc[MT][NT][4];
#pragma unroll
    for (int i = 0; i < MT; i++)
#pragma unroll
        for (int j = 0; j < NT; j++)
#pragma unroll
            for (int v = 0; v < 4; v++) acc[i][j][v] = 0.f;

#pragma unroll
    for (int s = 0; s < STAGES - 1; s++) {
        if (s < KT) load_stage(s, s);
        cp_commit();
    }

    for (int kt = 0; kt < KT; ++kt) {
        cp_wait<STAGES - 2>();
        __syncthreads();

        const int nk = kt + STAGES - 1;
        if (nk < KT) load_stage(nk % STAGES, nk);
        cp_commit();

        const uint32_t stb = sb + (kt % STAGES) * STG;
        const uint32_t stbB = stb + BM * 64;

#pragma unroll
        for (int ks = 0; ks < 2; ks++) {
            uint32_t ar[MT][4];
            uint32_t br[NP][4];
#pragma unroll
            for (int mt = 0; mt < MT; mt++) {
                int row = wm * WM + mt * 16 + l8 + (sel & 1) * 8;
                int ch = ks * 2 + (sel >> 1);
                ldsm4(ar[mt], stb + SW64(row * 64 + ch * 16));
            }
#pragma unroll
            for (int p = 0; p < NP; p++) {
                int row = wn * WN + p * 16 + l8 + (sel >> 1) * 8;
                int ch = ks * 2 + (sel & 1);
                ldsm4(br[p], stbB + SW64(row * 64 + ch * 16));
            }
#pragma unroll
            for (int mt = 0; mt < MT; mt++)
#pragma unroll
                for (int nt = 0; nt < NT; nt++) {
                    if (F16) mma_fp16(acc[mt][nt], ar[mt], &br[nt >> 1][(nt & 1) * 2]);
                    else     mma_bf16(acc[mt][nt], ar[mt], &br[nt >> 1][(nt & 1) * 2]);
                }
        }
    }

    const int g4 = lane >> 2;
    const int t4 = lane & 3;
#pragma unroll
    for (int mt = 0; mt < MT; mt++) {
#pragma unroll
        for (int nt = 0; nt < NT; nt++) {
            const int r = m0 + wm * WM + mt * 16 + g4;
            const int col = n0 + wn * WN + nt * 8 + 2 * t4;
            const float b0 = bias[col], b1 = bias[col + 1];
            float2 v0 = make_float2(acc[mt][nt][0] + b0, acc[mt][nt][1] + b1);
            float2 v1 = make_float2(acc[mt][nt][2] + b0, acc[mt][nt][3] + b1);
            *reinterpret_cast<float2*>(&C[(size_t)r * N + col]) = v0;
            *reinterpret_cast<float2*>(&C[(size_t)(r + 8) * N + col]) = v1;
        }
    }
}

// ---------------------------------------------------------------------------
// Conversions
// ---------------------------------------------------------------------------
// fp32 -> fp16 cast with zero padding (single-term)
__global__ void cast_f16(const float* __restrict__ src, __half* __restrict__ dst,
                         int K, int Kp, int total) {
    int idx = blockIdx.x * 256 + threadIdx.x;
    if (idx >= total) return;
    int r = idx / Kp, k = idx - r * Kp;
    float v = (k < K) ? src[(size_t)r * K + k] : 0.f;
    dst[(size_t)r * Kp + k] = __float2half(v);
}
// bf16 3-term splits for the recurrence
__global__ void splitA_bf(const float* __restrict__ src, __nv_bfloat16* __restrict__ dst,
                          int K, int Kp, int total) {
    int idx = blockIdx.x * 256 + threadIdx.x;
    if (idx >= total) return;
    int r = idx / Kp, k = idx - r * Kp;
    float v = (k < K) ? src[(size_t)r * K + k] : 0.f;
    __nv_bfloat16 hi = __float2bfloat16(v);
    __nv_bfloat16 lo = __float2bfloat16(v - __bfloat162float(hi));
    __nv_bfloat16* row = dst + (size_t)r * 3 * Kp;
    row[k] = hi; row[Kp + k] = lo; row[2 * Kp + k] = hi;
}
__global__ void splitB_bf(const float* __restrict__ src, __nv_bfloat16* __restrict__ dst,
                          int K, int Kp, int total) {
    int idx = blockIdx.x * 256 + threadIdx.x;
    if (idx >= total) return;
    int r = idx / Kp, k = idx - r * Kp;
    float v = (k < K) ? src[(size_t)r * K + k] : 0.f;
    __nv_bfloat16 hi = __float2bfloat16(v);
    __nv_bfloat16 lo = __float2bfloat16(v - __bfloat162float(hi));
    __nv_bfloat16* row = dst + (size_t)r * 3 * Kp;
    row[k] = hi; row[Kp + k] = hi; row[2 * Kp + k] = lo;
}

// ---------------------------------------------------------------------------
// Fused gates + recurrent-dropout + split-bf16 conversion of next h
// ---------------------------------------------------------------------------
__device__ __forceinline__ float sigf(float x) { return 1.f / (1.f + expf(-x)); }

__global__ void gates_kernel(const float* __restrict__ pi, const float* __restrict__ ps,
                             const float* __restrict__ c_in, float* __restrict__ c_out,
                             const float* __restrict__ mask, float* __restrict__ h_out,
                             __nv_bfloat16* __restrict__ Ah) {
    const int idx = blockIdx.x * blockDim.x + threadIdx.x;
    if (idx >= B_ * H_) return;
    const int b = idx / H_;
    const int j = idx - b * H_;
    const float* pib = pi + (size_t)b * 6 * H_;
    const float* psb = ps + (size_t)b * 5 * H_;

    const float i_g = sigf(pib[0 * H_ + j] + psb[0 * H_ + j]);
    const float f_g = sigf(pib[1 * H_ + j] + psb[1 * H_ + j]);
    const float m_i = tanhf(pib[2 * H_ + j] + psb[2 * H_ + j]);
    const float o_g = sigf(pib[3 * H_ + j] + psb[3 * H_ + j]);
    const float mem = i_g * m_i + f_g * c_in[idx];
    float out = o_g * tanhf(mem);
    const float hw = sigf(pib[4 * H_ + j] + psb[4 * H_ + j]);
    out = hw * out + (1.f - hw) * pib[5 * H_ + j];
    out *= mask[idx];
    c_out[idx] = mem;
    h_out[idx] = out;

    __nv_bfloat16 hi = __float2bfloat16(out);
    __nv_bfloat16 lo = __float2bfloat16(out - __bfloat162float(hi));
    __nv_bfloat16* row = Ah + (size_t)b * KTOT_ST;
    row[j] = hi; row[H_ + j] = lo; row[2 * H_ + j] = hi;
}

// ---------------------------------------------------------------------------
// fp32 SGEMM for the tiny output projection (N=151)
// ---------------------------------------------------------------------------
template<int BM, int BN, int TM, int TN>
__global__ void sgemm_bt(const float* __restrict__ A, const float* __restrict__ Bm,
                         const float* __restrict__ bias, float* __restrict__ C,
                         int M, int N, int K) {
    constexpr int BK = 16;
    constexpr int THREADS = (BM / TM) * (BN / TN);
    constexpr int PAD = 4;
    __shared__ float As[BK][BM + PAD];
    __shared__ float Bs[BK][BN + PAD];
    const int tid = threadIdx.x;
    const int m0 = blockIdx.y * BM;
    const int n0 = blockIdx.x * BN;
    const int tr = tid / (BN / TN);
    const int tc = tid % (BN / TN);
    float acc[TM][TN];
#pragma unroll
    for (int i = 0; i < TM; i++)
#pragma unroll
        for (int j = 0; j < TN; j++) acc[i][j] = 0.f;
    const int ktiles = (K + BK - 1) / BK;
    for (int kt = 0; kt < ktiles; ++kt) {
        const int k0 = kt * BK;
#pragma unroll
        for (int i = tid; i < BM * BK / 4; i += THREADS) {
            const int row = i / (BK / 4);
            const int kq = (i % (BK / 4)) * 4;
            float4 v = make_float4(0.f, 0.f, 0.f, 0.f);
            if (m0 + row < M && k0 + kq < K)
                v = *reinterpret_cast<const float4*>(&A[(size_t)(m0 + row) * K + k0 + kq]);
            As[kq + 0][row] = v.x; As[kq + 1][row] = v.y;
            As[kq + 2][row] = v.z; As[kq + 3][row] = v.w;
        }
#pragma unroll
        for (int i = tid; i < BN * BK / 4; i += THREADS) {
            const int row = i / (BK / 4);
            const int kq = (i % (BK / 4)) * 4;
            float4 v = make_float4(0.f, 0.f, 0.f, 0.f);
            if (n0 + row < N && k0 + kq < K)
                v = *reinterpret_cast<const float4*>(&Bm[(size_t)(n0 + row) * K + k0 + kq]);
            Bs[kq + 0][row] = v.x; Bs[kq + 1][row] = v.y;
            Bs[kq + 2][row] = v.z; Bs[kq + 3][row] = v.w;
        }
        __syncthreads();
#pragma unroll
        for (int kl = 0; kl < BK; ++kl) {
            float ra[TM], rb[TN];
#pragma unroll
            for (int i = 0; i < TM; i += 4) {
                float4 v = *reinterpret_cast<const float4*>(&As[kl][tr * TM + i]);
                ra[i] = v.x; ra[i + 1] = v.y; ra[i + 2] = v.z; ra[i + 3] = v.w;
            }
#pragma unroll
            for (int j = 0; j < TN; j += 4) {
                float4 v = *reinterpret_cast<const float4*>(&Bs[kl][tc * TN + j]);
                rb[j] = v.x; rb[j + 1] = v.y; rb[j + 2] = v.z; rb[j + 3] = v.w;
            }
#pragma unroll
            for (int i = 0; i < TM; i++)
#pragma unroll
                for (int j = 0; j < TN; j++)
                    acc[i][j] = fmaf(ra[i], rb[j], acc[i][j]);
        }
        __syncthreads();
    }
#pragma unroll
    for (int i = 0; i < TM; i++) {
        const int gm = m0 + tr * TM + i;
        if (gm >= M) continue;
#pragma unroll
        for (int j = 0; j < TN; j++) {
            const int gn = n0 + tc * TN + j;
            if (gn < N) C[(size_t)gm * N + gn] = acc[i][j] + bias[gn];
        }
    }
}

// ---------------------------------------------------------------------------
extern "C" void kernel_launch(void* const* d_in, const int* in_sizes, int n_in,
                              void* d_out, int out_size) {
    const float* x       = (const float*)d_in[0];
    const float* h0      = (const float*)d_in[1];
    const float* c0      = (const float*)d_in[2];
    const float* mask    = (const float*)d_in[3];
    const float* W_in    = (const float*)d_in[4];
    const float* b_in    = (const float*)d_in[5];
    const float* W_state = (const float*)d_in[6];
    const float* b_state = (const float*)d_in[7];
    const float* W_out   = (const float*)d_in[8];
    const float* b_out   = (const float*)d_in[9];
    float* out = (float*)d_out;

    __half *A2h, *B2h;
    __nv_bfloat16 *Bst, *Ah;
    float *PI, *PS, *HS, *CB;
    cudaGetSymbolAddress((void**)&A2h, g_A2h);
    cudaGetSymbolAddress((void**)&B2h, g_B2h);
    cudaGetSymbolAddress((void**)&Bst, g_Bst);
    cudaGetSymbolAddress((void**)&Ah, g_Ah);
    cudaGetSymbolAddress((void**)&PI, g_PI);
    cudaGetSymbolAddress((void**)&PS, g_PS);
    cudaGetSymbolAddress((void**)&HS, g_HS);
    cudaGetSymbolAddress((void**)&CB, g_CB);

    // One-time side-stream + events (no device memory involved)
    static cudaStream_t s2 = nullptr;
    static cudaEvent_t evFork = nullptr;
    static cudaEvent_t evPI[NCHUNK];
    if (!s2) {
        cudaStreamCreateWithFlags(&s2, cudaStreamNonBlocking);
        cudaEventCreateWithFlags(&evFork, cudaEventDisableTiming);
        for (int i = 0; i < NCHUNK; i++)
            cudaEventCreateWithFlags(&evPI[i], cudaEventDisableTiming);
    }

    constexpr int SMEM_BIG = (128 + 128) * 64 * 4;   // 65536
    constexpr int SMEM_REC = (64 + 128) * 64 * 4;    // 49152
    cudaFuncSetAttribute((const void*)mma_gemm<128, 128, 32, 64, 4, 2, 1>,
                         cudaFuncAttributeMaxDynamicSharedMemorySize, SMEM_BIG);
    cudaFuncSetAttribute((const void*)mma_gemm<64, 128, 32, 32, 4, 2, 0>,
                         cudaFuncAttributeMaxDynamicSharedMemorySize, SMEM_REC);

    const size_t BH = (size_t)B_ * H_;

    // ---- fork side stream off the capture stream ----
    cudaEventRecord(evFork, 0);
    cudaStreamWaitEvent(s2, evFork, 0);

    // ---- stream s2: input-projection pipeline (independent of recurrence) ----
    {
        int tot = T_ * B_ * KP_IN;
        cast_f16<<<(tot + 255) / 256, 256, 0, s2>>>(x, A2h, DIN_, KP_IN, tot);
    }
    {
        int tot = 6 * H_ * KP_IN;
        cast_f16<<<(tot + 255) / 256, 256, 0, s2>>>(W_in, B2h, DIN_, KP_IN, tot);
    }
    for (int c = 0; c < NCHUNK; c++) {
        dim3 grid((6 * H_) / 128, CH_ROWS / 128);
        mma_gemm<128, 128, 32, 64, 4, 2, 1><<<grid, 256, SMEM_BIG, s2>>>(
            A2h + (size_t)c * CH_ROWS * KP_IN, B2h, b_in,
            PI + (size_t)c * CH_ROWS * 6 * H_, CH_ROWS, 6 * H_, KP_IN);
        cudaEventRecord(evPI[c], s2);
    }

    // ---- capture stream: recurrence chain ----
    {
        int tot = 5 * H_ * H_;
        splitB_bf<<<(tot + 255) / 256, 256>>>(W_state, Bst, H_, H_, tot);
    }
    {
        int tot = B_ * H_;
        splitA_bf<<<(tot + 255) / 256, 256>>>(h0, Ah, H_, H_, tot);
    }

    for (int t = 0; t < T_; ++t) {
        const float* csrc = (t == 0) ? c0 : CB + (size_t)((t - 1) & 1) * BH;
        float* cdst = CB + (size_t)(t & 1) * BH;
        float* hdst = HS + (size_t)t * BH;
        const float* pit = PI + (size_t)t * B_ * 6 * H_;

        dim3 grid((5 * H_) / 128, B_ / 64);
        mma_gemm<64, 128, 32, 32, 4, 2, 0><<<grid, 256, SMEM_REC>>>(
            Ah, Bst, b_state, PS, B_, 5 * H_, KTOT_ST);

        if ((t & 3) == 0)                       // gates(t) needs PI chunk t/4
            cudaStreamWaitEvent(0, evPI[t >> 2], 0);
        gates_kernel<<<(B_ * H_) / 256, 256>>>(pit, PS, csrc, cdst, mask, hdst, Ah);
    }

    // Output projection (fp32, tiny N) — depends only on HS (capture stream)
    {
        dim3 grid((C_ + 63) / 64, (T_ * B_) / 64);
        sgemm_bt<64, 64, 4, 4><<<grid, 256>>>(HS, W_out, b_out, out,
                                              T_ * B_, C_, H_);
    }
}